// round 4
// baseline (speedup 1.0000x reference)
#include <cuda_runtime.h>
#include <cuda_fp16.h>
#include <cstdint>

#define N_NODES 8192
#define INC 512
#define OUTC 256
#define ALPHA 0.5f

// ---------------- scratch (device globals; no allocations allowed) ----------------
__device__ float    g_Wh  [N_NODES * OUTC];              // 8 MB fp32 Wh
__device__ __half   g_WhT [OUTC * N_NODES];              // 4 MB fp16 Wh^T (K-major [n][k])
__device__ float    g_Wh1 [N_NODES];
__device__ float    g_Wh2 [N_NODES];
__device__ float    g_gmax2;
__device__ uint32_t g_adjbits[N_NODES * (N_NODES / 32)]; // 8 MB packed adjacency

// ================= K0: pack adj -> bitmask (word w of row i = adj[i][32w..32w+31]) =======
__global__ void __launch_bounds__(256) k0_pack(const int* __restrict__ adj) {
    int idx = blockIdx.x * 256 + threadIdx.x;           // word index, 2M total
    size_t base = (size_t)idx * 32;
    uint32_t w = 0;
    #pragma unroll
    for (int q = 0; q < 8; q++) {
        int4 v = __ldcs(reinterpret_cast<const int4*>(adj + base + q * 4));
        w |= (uint32_t)(v.x > 0) << (q * 4 + 0);
        w |= (uint32_t)(v.y > 0) << (q * 4 + 1);
        w |= (uint32_t)(v.z > 0) << (q * 4 + 2);
        w |= (uint32_t)(v.w > 0) << (q * 4 + 3);
    }
    g_adjbits[idx] = w;
}

// ================= K1: Wh = h @ W  (fp32 SIMT, BM=128 BN=64 BK=16, 8x4 reg tile) =========
__global__ void __launch_bounds__(256) k1_gemm(const float* __restrict__ h, const float* __restrict__ W) {
    __shared__ float As[16][128];
    __shared__ float Bs[16][64];
    int tid = threadIdx.x;
    int tx = tid & 15, ty = tid >> 4;
    int bm0 = blockIdx.y * 128, bn0 = blockIdx.x * 64;

    float acc[8][4] = {};
    float4 pa[2], pb;
    {
        int r0 = tid >> 2, q0 = tid & 3;
        int r1 = (tid + 256) >> 2, q1 = tid & 3;
        pa[0] = *reinterpret_cast<const float4*>(h + (size_t)(bm0 + r0) * INC + q0 * 4);
        pa[1] = *reinterpret_cast<const float4*>(h + (size_t)(bm0 + r1) * INC + q1 * 4);
        int kk = tid >> 4, nq = tid & 15;
        pb = *reinterpret_cast<const float4*>(W + (size_t)kk * OUTC + bn0 + nq * 4);
    }
    for (int k0 = 0; k0 < INC; k0 += 16) {
        {
            int r0 = tid >> 2, q0 = tid & 3;
            int r1 = (tid + 256) >> 2;
            As[q0 * 4 + 0][r0] = pa[0].x; As[q0 * 4 + 1][r0] = pa[0].y;
            As[q0 * 4 + 2][r0] = pa[0].z; As[q0 * 4 + 3][r0] = pa[0].w;
            As[q0 * 4 + 0][r1] = pa[1].x; As[q0 * 4 + 1][r1] = pa[1].y;
            As[q0 * 4 + 2][r1] = pa[1].z; As[q0 * 4 + 3][r1] = pa[1].w;
            int kk = tid >> 4, nq = tid & 15;
            *reinterpret_cast<float4*>(&Bs[kk][nq * 4]) = pb;
        }
        __syncthreads();
        if (k0 + 16 < INC) {
            int kn = k0 + 16;
            int r0 = tid >> 2, q0 = tid & 3;
            int r1 = (tid + 256) >> 2;
            pa[0] = *reinterpret_cast<const float4*>(h + (size_t)(bm0 + r0) * INC + kn + q0 * 4);
            pa[1] = *reinterpret_cast<const float4*>(h + (size_t)(bm0 + r1) * INC + kn + q0 * 4);
            int kk = tid >> 4, nq = tid & 15;
            pb = *reinterpret_cast<const float4*>(W + (size_t)(kn + kk) * OUTC + bn0 + nq * 4);
        }
        #pragma unroll
        for (int kk = 0; kk < 16; kk++) {
            float4 a0 = *reinterpret_cast<const float4*>(&As[kk][ty * 8]);
            float4 a1 = *reinterpret_cast<const float4*>(&As[kk][ty * 8 + 4]);
            float4 bv = *reinterpret_cast<const float4*>(&Bs[kk][tx * 4]);
            float aa[8] = {a0.x, a0.y, a0.z, a0.w, a1.x, a1.y, a1.z, a1.w};
            float bb[4] = {bv.x, bv.y, bv.z, bv.w};
            #pragma unroll
            for (int i = 0; i < 8; i++)
                #pragma unroll
                for (int j = 0; j < 4; j++)
                    acc[i][j] += aa[i] * bb[j];
        }
        __syncthreads();
    }
    #pragma unroll
    for (int i = 0; i < 8; i++) {
        float4 v = {acc[i][0], acc[i][1], acc[i][2], acc[i][3]};
        *reinterpret_cast<float4*>(g_Wh + (size_t)(bm0 + ty * 8 + i) * OUTC + bn0 + tx * 4) = v;
    }
}

// ================= K2: Wh1/Wh2 GEMVs =================
__global__ void __launch_bounds__(256) k2_attvec(const float* __restrict__ a) {
    int tid = threadIdx.x, lid = tid & 31, wrp = tid >> 5;
    int r = blockIdx.x * 8 + wrp;
    const float* row = g_Wh + (size_t)r * OUTC;
    float s1 = 0.f, s2 = 0.f;
    #pragma unroll
    for (int t = 0; t < 8; t++) {
        int n = lid + t * 32;
        float w = row[n];
        s1 += w * a[n];
        s2 += w * a[OUTC + n];
    }
    #pragma unroll
    for (int o = 16; o > 0; o >>= 1) {
        s1 += __shfl_xor_sync(0xFFFFFFFF, s1, o);
        s2 += __shfl_xor_sync(0xFFFFFFFF, s2, o);
    }
    if (lid == 0) { g_Wh1[r] = s1; g_Wh2[r] = s2; }
}

// ================= K2b: global max of Wh2 =================
__global__ void __launch_bounds__(256) k2b_max() {
    __shared__ float red[256];
    int tid = threadIdx.x;
    float m = -1e30f;
    for (int j = tid; j < N_NODES; j += 256) m = fmaxf(m, g_Wh2[j]);
    red[tid] = m; __syncthreads();
    for (int o = 128; o > 0; o >>= 1) { if (tid < o) red[tid] = fmaxf(red[tid], red[tid + o]); __syncthreads(); }
    if (tid == 0) g_gmax2 = red[0];
}

// ================= K2c: WhT fp16 transpose =================
__global__ void k2c_transpose() {
    __shared__ float tile[32][33];
    int tx = threadIdx.x, ty = threadIdx.y;
    int i0 = blockIdx.x * 32, n0 = blockIdx.y * 32;
    #pragma unroll
    for (int k = 0; k < 32; k += 8)
        tile[ty + k][tx] = g_Wh[(size_t)(i0 + ty + k) * OUTC + n0 + tx];
    __syncthreads();
    #pragma unroll
    for (int k = 0; k < 32; k += 8)
        g_WhT[(size_t)(n0 + ty + k) * N_NODES + i0 + tx] = __float2half(tile[tx][ty + k]);
}

// ================= K34 fused: softmax-numerator generation + HMMA GEMM + normalize ======
// BM=64, BN=256, BK=32. A tile built in SMEM from adj bits + Wh1/Wh2 (no g_P!).
// Row sums accumulate in registers (CTA owns full rows), epilogue normalizes + relu.

#define F_BM 64
#define F_BK 32
#define F_NK (N_NODES / F_BK)            // 256
#define F_ROWB 80                        // padded A/B row bytes (40 halves)
#define F_A_BYTES (F_BM * F_ROWB)        // 5120
#define F_B_BYTES (256 * F_ROWB)         // 20480
#define F_BITS_STRIDE 260                // words per row (padded: 16B-aligned, conflict-free)

#define WH2S_OFF 0                        // 32768 B (8192 floats)
#define BITS_OFF 32768                    // 64*260*4 = 66560 B
#define ABUF_OFF 99328                    // 2 * 5120
#define BBUF_OFF 109568                   // 3 * 20480
#define SUMS_OFF 171008                   // 64*4 floats
#define F_SMEM_TOT 172032

__device__ __forceinline__ uint32_t smem_u32(const void* p) {
    uint32_t a;
    asm("{ .reg .u64 t; cvta.to.shared.u64 t, %1; cvt.u32.u64 %0, t; }" : "=r"(a) : "l"(p));
    return a;
}
__device__ __forceinline__ void cp16(uint32_t s, const void* g) {
    asm volatile("cp.async.cg.shared.global [%0], [%1], 16;" :: "r"(s), "l"(g) : "memory");
}
__device__ __forceinline__ void cp_commit() { asm volatile("cp.async.commit_group;" ::: "memory"); }
__device__ __forceinline__ void cp_wait1()  { asm volatile("cp.async.wait_group 1;" ::: "memory"); }
__device__ __forceinline__ void cp_wait0()  { asm volatile("cp.async.wait_group 0;" ::: "memory"); }

__device__ __forceinline__ void ldsm4(uint32_t* r, uint32_t addr) {
    asm volatile("ldmatrix.sync.aligned.m8n8.x4.shared.b16 {%0,%1,%2,%3}, [%4];"
                 : "=r"(r[0]), "=r"(r[1]), "=r"(r[2]), "=r"(r[3]) : "r"(addr));
}
__device__ __forceinline__ void hmma16816(float* c, const uint32_t* a, const uint32_t* b) {
    asm volatile("mma.sync.aligned.m16n8k16.row.col.f32.f16.f16.f32 "
                 "{%0,%1,%2,%3}, {%4,%5,%6,%7}, {%8,%9}, {%0,%1,%2,%3};"
                 : "+f"(c[0]), "+f"(c[1]), "+f"(c[2]), "+f"(c[3])
                 : "r"(a[0]), "r"(a[1]), "r"(a[2]), "r"(a[3]), "r"(b[0]), "r"(b[1]));
}

__device__ __forceinline__ void f_loadB(uint32_t stageBase, int k0, int t) {
    int r = t >> 2, cb = (t & 3) * 8;
    #pragma unroll
    for (int q = 0; q < 4; q++) {
        int n = r + 64 * q;
        cp16(stageBase + n * F_ROWB + (t & 3) * 16,
             g_WhT + (size_t)n * N_NODES + k0 + cb);
    }
}

__global__ void __launch_bounds__(256, 1) k34_fused(float* __restrict__ out) {
    extern __shared__ char smem[];
    uint32_t sbase = smem_u32(smem);
    int t = threadIdx.x, wid = t >> 5, l = t & 31;
    int rowBase = blockIdx.x * F_BM;
    int wm = wid >> 2, wn = wid & 3;
    int m0 = wm * 32, n0 = wn * 64;

    // ---- preload Wh2 (32KB) and this CTA's adjacency bits (64 rows x 256 words) ----
    float* wh2s = reinterpret_cast<float*>(smem + WH2S_OFF);
    {
        const float4* src = reinterpret_cast<const float4*>(g_Wh2);
        #pragma unroll
        for (int q = 0; q < 8; q++)
            reinterpret_cast<float4*>(wh2s)[t + q * 256] = src[t + q * 256];
        #pragma unroll
        for (int q = 0; q < 16; q++) {
            int i4 = t + q * 256;                  // uint4 index, 4096 total
            int row = i4 >> 6, col4 = i4 & 63;
            uint4 v = *reinterpret_cast<const uint4*>(
                g_adjbits + (size_t)(rowBase + row) * 256 + col4 * 4);
            *reinterpret_cast<uint4*>(smem + BITS_OFF + row * (F_BITS_STRIDE * 4) + col4 * 16) = v;
        }
    }

    // per-thread A-gen constants: row r = t>>2, cols c0..c0+7 of each chunk
    int r = t >> 2, c0 = (t & 3) * 8;
    float wh1r = g_Wh1[rowBase + r];
    float xB = wh1r + g_gmax2;
    float Br = xB > 0.f ? xB : ALPHA * xB;
    float srow_part = 0.f;

    float acc[2][8][4];
    #pragma unroll
    for (int mi = 0; mi < 2; mi++)
        #pragma unroll
        for (int ni = 0; ni < 8; ni++)
            #pragma unroll
            for (int c = 0; c < 4; c++) acc[mi][ni][c] = 0.f;

    int sub = l >> 3, lr = l & 7;
    int aRowOff = (sub & 1) * 8 + lr;
    int aByte   = (sub >> 1) * 16;
    int bRowOff = ((sub >> 1) & 1) * 8 + lr;
    int bByte   = (sub & 1) * 16;

    // prologue: B stages 0,1 in flight
    f_loadB(sbase + BBUF_OFF, 0, t);                      cp_commit();
    f_loadB(sbase + BBUF_OFF + F_B_BYTES, F_BK, t);       cp_commit();
    __syncthreads();   // bits + wh2s visible

    int cs = 0, ls = 2;
    for (int kc = 0; kc < F_NK; kc++) {
        if (kc == F_NK - 1) cp_wait0(); else cp_wait1();  // B stage kc resident (tail-safe)
        __syncthreads();                                  // prev MMA done (A WAR + B stage reuse)
        if (kc + 2 < F_NK) {
            f_loadB(sbase + BBUF_OFF + ls * F_B_BYTES, (kc + 2) * F_BK, t);
            cp_commit();
        }

        // ---- generate A tile chunk kc: p = bit ? exp(lrelu(wh1+wh2)-B) : 0 ----
        {
            uint32_t word = *reinterpret_cast<const uint32_t*>(
                smem + BITS_OFF + r * (F_BITS_STRIDE * 4) + kc * 4);
            const float* w2 = wh2s + kc * F_BK + c0;
            float4 wa = *reinterpret_cast<const float4*>(w2);
            float4 wb = *reinterpret_cast<const float4*>(w2 + 4);
            float p[8];
            float ww[8] = {wa.x, wa.y, wa.z, wa.w, wb.x, wb.y, wb.z, wb.w};
            #pragma unroll
            for (int jj = 0; jj < 8; jj++) {
                float x = wh1r + ww[jj];
                float e = x > 0.f ? x : ALPHA * x;
                float pe = __expf(e - Br);
                p[jj] = ((word >> (c0 + jj)) & 1u) ? pe : 0.f;
            }
            srow_part += (p[0] + p[1]) + (p[2] + p[3]) + (p[4] + p[5]) + (p[6] + p[7]);
            __half2 h0 = __floats2half2_rn(p[0], p[1]);
            __half2 h1 = __floats2half2_rn(p[2], p[3]);
            __half2 h2 = __floats2half2_rn(p[4], p[5]);
            __half2 h3 = __floats2half2_rn(p[6], p[7]);
            uint4 pk;
            pk.x = *reinterpret_cast<uint32_t*>(&h0);
            pk.y = *reinterpret_cast<uint32_t*>(&h1);
            pk.z = *reinterpret_cast<uint32_t*>(&h2);
            pk.w = *reinterpret_cast<uint32_t*>(&h3);
            *reinterpret_cast<uint4*>(smem + ABUF_OFF + (kc & 1) * F_A_BYTES
                                      + r * F_ROWB + (t & 3) * 16) = pk;
        }
        __syncthreads();                                  // A tile visible

        uint32_t aT = sbase + ABUF_OFF + (kc & 1) * F_A_BYTES;
        uint32_t bT = sbase + BBUF_OFF + cs * F_B_BYTES;
        #pragma unroll
        for (int ks = 0; ks < 2; ks++) {
            int ksb = ks * 32;
            uint32_t afr[2][4], bfr[4][4];
            #pragma unroll
            for (int mi = 0; mi < 2; mi++)
                ldsm4(afr[mi], aT + (m0 + mi * 16 + aRowOff) * F_ROWB + ksb + aByte);
            #pragma unroll
            for (int pi = 0; pi < 4; pi++)
                ldsm4(bfr[pi], bT + (n0 + pi * 16 + bRowOff) * F_ROWB + ksb + bByte);
            #pragma unroll
            for (int mi = 0; mi < 2; mi++)
                #pragma unroll
                for (int ni = 0; ni < 8; ni++)
                    hmma16816(acc[mi][ni], afr[mi], &bfr[ni >> 1][(ni & 1) * 2]);
        }
        cs = (cs == 2) ? 0 : cs + 1;
        ls = (ls == 2) ? 0 : ls + 1;
    }

    // ---- row-sum reduction (4 partials per row) ----
    float* sums = reinterpret_cast<float*>(smem + SUMS_OFF);
    __syncthreads();
    sums[r * 4 + (t & 3)] = srow_part;
    __syncthreads();
    if (t < 64) {
        float tot = sums[t * 4] + sums[t * 4 + 1] + sums[t * 4 + 2] + sums[t * 4 + 3];
        sums[t * 4] = 1.0f / tot;
    }
    __syncthreads();

    // ---- epilogue: normalize + relu + store ----
    #pragma unroll
    for (int mi = 0; mi < 2; mi++)
        #pragma unroll
        for (int hh = 0; hh < 2; hh++) {
            int lrow = m0 + mi * 16 + hh * 8 + (l >> 2);
            float iv = sums[lrow * 4];
            int row = rowBase + lrow;
            #pragma unroll
            for (int ni = 0; ni < 8; ni++) {
                int col = n0 + ni * 8 + (l & 3) * 2;
                float2 v;
                v.x = fmaxf(acc[mi][ni][hh * 2 + 0] * iv, 0.f);
                v.y = fmaxf(acc[mi][ni][hh * 2 + 1] * iv, 0.f);
                *reinterpret_cast<float2*>(out + (size_t)row * OUTC + col) = v;
            }
        }
}

// ================= launch =================
extern "C" void kernel_launch(void* const* d_in, const int* in_sizes, int n_in,
                              void* d_out, int out_size) {
    const float* h   = (const float*)d_in[0];
    const int*   adj = (const int*)d_in[1];
    const float* W   = (const float*)d_in[2];
    const float* a   = (const float*)d_in[3];
    float* out = (float*)d_out;

    k0_pack<<<N_NODES * (N_NODES / 32) / 256, 256>>>(adj);
    k1_gemm<<<dim3(OUTC / 64, N_NODES / 128), 256>>>(h, W);
    k2_attvec<<<N_NODES / 8, 256>>>(a);
    k2b_max<<<1, 256>>>();
    k2c_transpose<<<dim3(N_NODES / 32, OUTC / 32), dim3(32, 8)>>>();

    static bool attr_set = false;
    if (!attr_set) {
        cudaFuncSetAttribute(k34_fused, cudaFuncAttributeMaxDynamicSharedMemorySize, F_SMEM_TOT);
        attr_set = true;
    }
    k34_fused<<<N_NODES / F_BM, 256, F_SMEM_TOT>>>(out);
}